// round 1
// baseline (speedup 1.0000x reference)
#include <cuda_runtime.h>
#include <cstdint>

// Problem constants
#define N_NODES 2048
#define K_TOTAL 3072      // = B*L = 128*24 (C_IN)
#define KC      64        // K elements per k-chunk
#define NKC     (K_TOTAL / KC)   // 48 k-chunks
#define NBN     8         // n-chunks of 256 nodes
#define ROWS    3072      // output rows = B*L
#define OUT_ELEMS (ROWS * N_NODES)   // 6,291,456

// Scratch (device globals: no allocation allowed). Fully overwritten every launch.
__device__ float g_part[NKC * 8 * N_NODES];   // 3 MB partial conv sums
__device__ float g_per_node[N_NODES];         // 8 KB per-node scalars

// ---------------------------------------------------------------------------
// K1: partial skinny GEMM. conv_part[kc][j][n] = sum_{k in chunk} x[k][n]*Wc[k][j]
// Thread = one node column; warp reads coalesced 128B lines of x.
// ---------------------------------------------------------------------------
__global__ __launch_bounds__(256) void k_gemm_partial(
    const float* __restrict__ x, const float* __restrict__ Wc)
{
    __shared__ float sW[KC * 8];   // 2 KB

    const int tid  = threadIdx.x;
    const int nblk = blockIdx.x;   // 0..7
    const int kblk = blockIdx.y;   // 0..47
    const int k0   = kblk * KC;

    // Stage Wc chunk (contiguous 512 floats) into shared
    const float* wsrc = Wc + (size_t)k0 * 8;
    #pragma unroll
    for (int i = tid; i < KC * 8; i += 256) sW[i] = wsrc[i];
    __syncthreads();

    const int n = nblk * 256 + tid;
    const float* xp = x + (size_t)k0 * N_NODES + n;

    float acc[8];
    #pragma unroll
    for (int j = 0; j < 8; j++) acc[j] = 0.0f;

    // Batch 8 loads ahead of the FMAs -> MLP ~ 8 per thread
    for (int kk = 0; kk < KC; kk += 8) {
        float xv[8];
        #pragma unroll
        for (int u = 0; u < 8; u++)
            xv[u] = __ldg(xp + (size_t)(kk + u) * N_NODES);
        #pragma unroll
        for (int u = 0; u < 8; u++) {
            #pragma unroll
            for (int j = 0; j < 8; j++)
                acc[j] = fmaf(xv[u], sW[(kk + u) * 8 + j], acc[j]);
        }
    }

    float* gp = g_part + ((size_t)kblk * 8) * N_NODES + n;
    #pragma unroll
    for (int j = 0; j < 8; j++)
        gp[(size_t)j * N_NODES] = acc[j];
}

// ---------------------------------------------------------------------------
// K2: reduce the 48 partials per (n,j), add bc, run the folded MLP, store
// per_node[n]. combined=[conv,conv] => effective W1 = W1[0:8]+W1[8:16].
// ---------------------------------------------------------------------------
__global__ __launch_bounds__(64) void k_reduce_mlp(
    const float* __restrict__ bc, const float* __restrict__ W1,
    const float* __restrict__ b1, const float* __restrict__ W2,
    const float* __restrict__ b2)
{
    __shared__ float sWeff[256];   // Weff[j][m] = W1[j*32+m] + W1[(j+8)*32+m]
    __shared__ float sb1[32];
    __shared__ float sW2[32];

    const int tid = threadIdx.x;   // 64 threads
    #pragma unroll
    for (int i = tid; i < 256; i += 64)
        sWeff[i] = W1[i] + W1[i + 256];
    if (tid < 32) { sb1[tid] = b1[tid]; sW2[tid] = W2[tid]; }
    __syncthreads();

    const int n = blockIdx.x * 64 + tid;   // grid = 32 -> n in [0, 2048)

    float conv[8];
    #pragma unroll
    for (int j = 0; j < 8; j++) conv[j] = 0.0f;

    #pragma unroll 4
    for (int kc = 0; kc < NKC; kc++) {
        const float* p = g_part + ((size_t)kc * 8) * N_NODES + n;
        #pragma unroll
        for (int j = 0; j < 8; j++)
            conv[j] += p[(size_t)j * N_NODES];
    }
    #pragma unroll
    for (int j = 0; j < 8; j++) conv[j] += __ldg(bc + j);

    float pn = __ldg(b2);
    #pragma unroll 4
    for (int m = 0; m < 32; m++) {
        float h = sb1[m];
        #pragma unroll
        for (int j = 0; j < 8; j++)
            h = fmaf(conv[j], sWeff[j * 32 + m], h);
        h = fmaxf(h, 0.01f * h);         // leaky_relu, slope 0.01
        pn = fmaf(h, sW2[m], pn);
    }
    g_per_node[n] = pn;
}

// ---------------------------------------------------------------------------
// K3: broadcast per_node over all 3072 rows. Pure write-bound, float4 stores.
// out[r*2048 + n] = per_node[n]; as float4: out4[i] = pn4[i & 511].
// ---------------------------------------------------------------------------
__global__ __launch_bounds__(256) void k_broadcast(float4* __restrict__ out)
{
    const float4* pn4 = reinterpret_cast<const float4*>(g_per_node);
    int idx = blockIdx.x * 1024 + threadIdx.x;
    #pragma unroll
    for (int i = 0; i < 4; i++) {
        int id = idx + i * 256;
        out[id] = __ldg(pn4 + (id & 511));
    }
}

// ---------------------------------------------------------------------------
// Inputs (metadata order): 0:x 1:edge_index(i64,unused) 2:edge_attr(unused)
//                          3:Wc 4:bc 5:W1 6:b1 7:W2 8:b2
// ---------------------------------------------------------------------------
extern "C" void kernel_launch(void* const* d_in, const int* in_sizes, int n_in,
                              void* d_out, int out_size)
{
    const float* x  = (const float*)d_in[0];
    const float* Wc = (const float*)d_in[3];
    const float* bc = (const float*)d_in[4];
    const float* W1 = (const float*)d_in[5];
    const float* b1 = (const float*)d_in[6];
    const float* W2 = (const float*)d_in[7];
    const float* b2 = (const float*)d_in[8];
    float* out = (float*)d_out;

    k_gemm_partial<<<dim3(NBN, NKC), 256>>>(x, Wc);
    k_reduce_mlp<<<32, 64>>>(bc, W1, b1, W2, b2);
    // OUT_ELEMS/4 float4 = 1,572,864 ; 1536 blocks * 256 thr * 4 f4 each
    k_broadcast<<<1536, 256>>>(reinterpret_cast<float4*>(out));
}

// round 2
// speedup vs baseline: 1.1136x; 1.1136x over previous
#include <cuda_runtime.h>
#include <cstdint>

// Problem constants
#define N_NODES 2048
#define NF4     512             // N_NODES / 4 float4 columns
#define K_TOTAL 3072            // B*L
#define KC      48              // k rows per chunk
#define NKC     64              // chunks (KC*NKC == K_TOTAL)
#define ROWS    3072

// Scratch device globals (no allocation allowed). Fully overwritten each launch.
__device__ float g_part[NKC * 8 * N_NODES];   // 4 MB partial conv sums
__device__ float g_per_node[N_NODES];         // 8 KB per-node scalars

// ---- packed f32x2 helpers (Blackwell) -------------------------------------
__device__ __forceinline__ unsigned long long pack2(float a, float b) {
    unsigned long long r;
    asm("mov.b64 %0, {%1, %2};" : "=l"(r) : "f"(a), "f"(b));
    return r;
}
__device__ __forceinline__ unsigned long long fma2(unsigned long long a,
                                                   unsigned long long b,
                                                   unsigned long long c) {
    unsigned long long d;
    asm("fma.rn.f32x2 %0, %1, %2, %3;" : "=l"(d) : "l"(a), "l"(b), "l"(c));
    return d;
}
__device__ __forceinline__ void unpack2(unsigned long long v, float& a, float& b) {
    asm("mov.b64 {%0, %1}, %2;" : "=f"(a), "=f"(b) : "l"(v));
}

// ---------------------------------------------------------------------------
// K1: partial skinny GEMM with float4 loads + packed f32x2 FMAs.
// Thread = one float4 column (4 nodes) over KC k-rows.
// grid = (4 n-blocks of 128 f4-cols, 64 k-chunks), block = 128 threads.
// ---------------------------------------------------------------------------
__global__ __launch_bounds__(128) void k_gemm_partial(
    const float4* __restrict__ x4, const float* __restrict__ Wc)
{
    // Wc chunk, each value duplicated into an f32x2 pair: sWd[2*i] = sWd[2*i+1] = w[i]
    __shared__ float sWd[KC * 8 * 2];   // 3 KB

    const int tid  = threadIdx.x;
    const int nblk = blockIdx.x;        // 0..3
    const int kblk = blockIdx.y;        // 0..63
    const int k0   = kblk * KC;

    const float* wsrc = Wc + (size_t)k0 * 8;
    #pragma unroll
    for (int i = tid; i < KC * 8 * 2; i += 128) sWd[i] = wsrc[i >> 1];
    __syncthreads();

    const int c = nblk * 128 + tid;     // f4 column 0..511
    const float4* xp = x4 + (size_t)k0 * NF4 + c;
    const unsigned long long* wp2 = reinterpret_cast<const unsigned long long*>(sWd);

    unsigned long long accp[2][8];      // [pair][j]; pair0 = nodes {4c,4c+1}
    #pragma unroll
    for (int p = 0; p < 2; p++)
        #pragma unroll
        for (int j = 0; j < 8; j++) accp[p][j] = 0ull;

    #pragma unroll
    for (int kk = 0; kk < KC; kk += 12) {
        float4 xv[12];
        #pragma unroll
        for (int u = 0; u < 12; u++)
            xv[u] = __ldg(xp + (size_t)(kk + u) * NF4);
        #pragma unroll
        for (int u = 0; u < 12; u++) {
            unsigned long long lo = pack2(xv[u].x, xv[u].y);
            unsigned long long hi = pack2(xv[u].z, xv[u].w);
            const unsigned long long* w = wp2 + (kk + u) * 8;
            #pragma unroll
            for (int j = 0; j < 8; j++) {
                unsigned long long wj = w[j];
                accp[0][j] = fma2(lo, wj, accp[0][j]);
                accp[1][j] = fma2(hi, wj, accp[1][j]);
            }
        }
    }

    float4* gp4 = reinterpret_cast<float4*>(g_part);
    #pragma unroll
    for (int j = 0; j < 8; j++) {
        float4 o;
        unpack2(accp[0][j], o.x, o.y);
        unpack2(accp[1][j], o.z, o.w);
        gp4[(size_t)(kblk * 8 + j) * NF4 + c] = o;
    }
}

// ---------------------------------------------------------------------------
// K2: reduce 64 partials per (n,j), add bc, folded MLP, write per_node[n].
// Split-k: 2 halves of 32 chunks per node, combined through SMEM.
// grid = 16 blocks x 256 threads (128 nodes/block).
// ---------------------------------------------------------------------------
__global__ __launch_bounds__(256) void k_reduce_mlp(
    const float* __restrict__ bc, const float* __restrict__ W1,
    const float* __restrict__ b1, const float* __restrict__ W2,
    const float* __restrict__ b2)
{
    __shared__ float sWeff[256];        // W1[0:8] + W1[8:16] folded
    __shared__ float sb1[32];
    __shared__ float sW2v[32];
    __shared__ float sred[128 * 9];     // padded to kill bank conflicts

    const int tid  = threadIdx.x;
    const int half = tid >> 7;          // 0 or 1
    const int ln   = tid & 127;
    const int n    = blockIdx.x * 128 + ln;

    if (tid < 256) sWeff[tid] = W1[tid] + W1[tid + 256];
    if (tid < 32) { sb1[tid] = b1[tid]; sW2v[tid] = W2[tid]; }

    float conv[8];
    #pragma unroll
    for (int j = 0; j < 8; j++) conv[j] = 0.0f;

    const int kc0 = half * 32;
    #pragma unroll 4
    for (int kc = kc0; kc < kc0 + 32; kc++) {
        const float* p = g_part + (size_t)(kc * 8) * N_NODES + n;
        #pragma unroll
        for (int j = 0; j < 8; j++)
            conv[j] += p[(size_t)j * N_NODES];
    }

    if (half == 1) {
        #pragma unroll
        for (int j = 0; j < 8; j++) sred[ln * 9 + j] = conv[j];
    }
    __syncthreads();
    if (half == 0) {
        #pragma unroll
        for (int j = 0; j < 8; j++)
            conv[j] += sred[ln * 9 + j] + __ldg(bc + j);

        float pn = __ldg(b2);
        #pragma unroll 4
        for (int m = 0; m < 32; m++) {
            float h = sb1[m];
            #pragma unroll
            for (int j = 0; j < 8; j++)
                h = fmaf(conv[j], sWeff[j * 32 + m], h);
            h = fmaxf(h, 0.01f * h);    // leaky_relu
            pn = fmaf(h, sW2v[m], pn);
        }
        g_per_node[n] = pn;
    }
}

// ---------------------------------------------------------------------------
// K3: broadcast per_node over 3072 rows. One register-held float4 per thread,
// 16 streaming 128-bit stores. grid = 384 x 256.
// ---------------------------------------------------------------------------
__global__ __launch_bounds__(256) void k_broadcast(float4* __restrict__ out)
{
    const int c  = (blockIdx.x & 1) * 256 + threadIdx.x;  // f4 column 0..511
    const int r0 = (blockIdx.x >> 1) * 16;                // row group
    const float4 v = __ldg(reinterpret_cast<const float4*>(g_per_node) + c);
    float4* o = out + (size_t)r0 * NF4 + c;
    #pragma unroll
    for (int i = 0; i < 16; i++)
        __stcs(o + (size_t)i * NF4, v);
}

// ---------------------------------------------------------------------------
// Inputs: 0:x 1:edge_index(unused) 2:edge_attr(unused) 3:Wc 4:bc 5:W1 6:b1 7:W2 8:b2
// ---------------------------------------------------------------------------
extern "C" void kernel_launch(void* const* d_in, const int* in_sizes, int n_in,
                              void* d_out, int out_size)
{
    const float4* x4 = (const float4*)d_in[0];
    const float*  Wc = (const float*)d_in[3];
    const float*  bc = (const float*)d_in[4];
    const float*  W1 = (const float*)d_in[5];
    const float*  b1 = (const float*)d_in[6];
    const float*  W2 = (const float*)d_in[7];
    const float*  b2 = (const float*)d_in[8];
    float* out = (float*)d_out;

    k_gemm_partial<<<dim3(4, NKC), 128>>>(x4, Wc);
    k_reduce_mlp<<<16, 256>>>(bc, W1, b1, W2, b2);
    k_broadcast<<<384, 256>>>(reinterpret_cast<float4*>(out));
}